// round 1
// baseline (speedup 1.0000x reference)
#include <cuda_runtime.h>
#include <math.h>

#define NN 50000
#define NE 800000
#define KF 128          // IN_F
#define HF 128          // HEADS * OUT_F
#define NH 4
#define OF 32
#define EF 32

// ---------------- scratch (device globals: allocation-free) ----------------
__device__ float g_ht[(size_t)NN * HF];       // 25.6 MB
__device__ float g_ai[NN * NH];
__device__ float g_aj[NN * NH];
__device__ float g_e[(size_t)NE * NH];        // 12.8 MB (e scores, then e_exp)
__device__ float g_denom[NN * NH];
__device__ float g_vc[NH * EF + NH];          // v[h][k] at h*32+k, c[h] at 128+h
__device__ unsigned int g_maxbits;

// orderable-uint encoding of float for atomicMax over mixed signs
__device__ __forceinline__ unsigned f2o(float x) {
    unsigned u = __float_as_uint(x);
    return (u & 0x80000000u) ? ~u : (u | 0x80000000u);
}
__device__ __forceinline__ float o2f(unsigned u) {
    return __uint_as_float((u & 0x80000000u) ? (u & 0x7fffffffu) : ~u);
}

// ---------------- kernel 0: init (zero denom, compute v/c, reset max) -----
__global__ void k_init(const float* __restrict__ eW, const float* __restrict__ a,
                       const float* __restrict__ eb) {
    int idx = blockIdx.x * blockDim.x + threadIdx.x;
    for (int i = idx; i < NN * NH; i += gridDim.x * blockDim.x) g_denom[i] = 0.0f;
    if (blockIdx.x == 0) {
        int t = threadIdx.x;
        if (t < NH * EF) {                 // v[h][k] = sum_f eW[k, h*32+f] * a_e[h][f]
            int h = t >> 5, k = t & 31;
            float s = 0.0f;
            #pragma unroll
            for (int f = 0; f < OF; f++)
                s += eW[k * HF + h * OF + f] * a[h * 96 + 64 + f];
            g_vc[t] = s;
        } else if (t < NH * EF + NH) {     // c[h] = sum_f eb[h*32+f] * a_e[h][f]
            int h = t - NH * EF;
            float s = 0.0f;
            #pragma unroll
            for (int f = 0; f < OF; f++)
                s += eb[h * OF + f] * a[h * 96 + 64 + f];
            g_vc[NH * EF + h] = s;
        } else if (t == NH * EF + NH) {
            g_maxbits = 0u;                // < f2o(any float)
        }
    }
}

// ---------------- kernel 1: ht = h @ W (128x128 tile SGEMM, 8x8/thread) ---
__global__ void k_gemm(const float* __restrict__ h, const float* __restrict__ W) {
    __shared__ float As[8][128];
    __shared__ float Bs[8][128];
    int row0 = blockIdx.x * 128;
    int t = threadIdx.x;
    int tr = t >> 4;       // 0..15
    int tc = t & 15;       // 0..15
    float acc[8][8];
    #pragma unroll
    for (int i = 0; i < 8; i++)
        #pragma unroll
        for (int j = 0; j < 8; j++) acc[i][j] = 0.0f;

    for (int k0 = 0; k0 < KF; k0 += 8) {
        // load A tile transposed: As[k][r] = h[row0+r][k0+k]
        {
            int r = t >> 1;
            int kk = (t & 1) * 4;
            float4 hv = make_float4(0.f, 0.f, 0.f, 0.f);
            if (row0 + r < NN)
                hv = *(const float4*)(h + (size_t)(row0 + r) * KF + k0 + kk);
            As[kk + 0][r] = hv.x; As[kk + 1][r] = hv.y;
            As[kk + 2][r] = hv.z; As[kk + 3][r] = hv.w;
            // load B tile: Bs[k][j] = W[(k0+k)*128 + j]
            int o = t * 4;
            *(float4*)(&Bs[0][0] + o) = *(const float4*)(W + (size_t)k0 * HF + o);
        }
        __syncthreads();
        #pragma unroll
        for (int k = 0; k < 8; k++) {
            float av[8], bv[8];
            *(float4*)(av)     = *(const float4*)&As[k][tr * 8];
            *(float4*)(av + 4) = *(const float4*)&As[k][tr * 8 + 4];
            *(float4*)(bv)     = *(const float4*)&Bs[k][tc * 8];
            *(float4*)(bv + 4) = *(const float4*)&Bs[k][tc * 8 + 4];
            #pragma unroll
            for (int i = 0; i < 8; i++)
                #pragma unroll
                for (int j = 0; j < 8; j++)
                    acc[i][j] += av[i] * bv[j];
        }
        __syncthreads();
    }
    #pragma unroll
    for (int i = 0; i < 8; i++) {
        int r = row0 + tr * 8 + i;
        if (r < NN) {
            float4* dst = (float4*)(g_ht + (size_t)r * HF + tc * 8);
            dst[0] = make_float4(acc[i][0], acc[i][1], acc[i][2], acc[i][3]);
            dst[1] = make_float4(acc[i][4], acc[i][5], acc[i][6], acc[i][7]);
        }
    }
}

// ---------------- kernel 2: alpha_i / alpha_j per node ---------------------
__global__ void k_alpha(const float* __restrict__ a) {
    int n = blockIdx.x * 2 + (threadIdx.x >> 7);
    if (n >= NN) return;
    int t = threadIdx.x & 127;
    int h = t >> 5, f = t & 31;
    float x = g_ht[(size_t)n * HF + t];
    float vi = x * __ldg(&a[h * 96 + f]);
    float vj = x * __ldg(&a[h * 96 + 32 + f]);
    #pragma unroll
    for (int o = 16; o; o >>= 1) {
        vi += __shfl_down_sync(0xffffffffu, vi, o);
        vj += __shfl_down_sync(0xffffffffu, vj, o);
    }
    if (f == 0) {
        g_ai[n * NH + h] = vi;
        g_aj[n * NH + h] = vj;
    }
}

// ---------------- kernel 3: edge scores e + global max ---------------------
__global__ void k_edge(const int* __restrict__ ei, const float* __restrict__ ea) {
    __shared__ float svc[NH * EF + NH];
    if (threadIdx.x < NH * EF + NH) svc[threadIdx.x] = g_vc[threadIdx.x];
    __syncthreads();

    int e = blockIdx.x * blockDim.x + threadIdx.x;
    float m = -1e30f;
    if (e < NE) {
        int row = ei[e];
        int col = ei[NE + e];
        float x[EF];
        #pragma unroll
        for (int q = 0; q < 8; q++)
            *(float4*)(x + q * 4) = *(const float4*)(ea + (size_t)e * EF + q * 4);
        float4 ai = *(const float4*)(g_ai + (size_t)row * NH);
        float4 aj = *(const float4*)(g_aj + (size_t)col * NH);
        const float* aip = (const float*)&ai;
        const float* ajp = (const float*)&aj;
        float ev[NH];
        #pragma unroll
        for (int h = 0; h < NH; h++) {
            float s = svc[NH * EF + h];
            #pragma unroll
            for (int k = 0; k < EF; k++) s += x[k] * svc[h * EF + k];
            s += aip[h] + ajp[h];
            s = (s > 0.0f) ? s : 0.2f * s;     // leaky_relu(0.2)
            ev[h] = s;
            m = fmaxf(m, s);
        }
        *(float4*)(g_e + (size_t)e * NH) = make_float4(ev[0], ev[1], ev[2], ev[3]);
    }
    // block max -> atomicMax
    __shared__ float smax[256];
    smax[threadIdx.x] = m;
    __syncthreads();
    for (int s = 128; s; s >>= 1) {
        if (threadIdx.x < s) smax[threadIdx.x] = fmaxf(smax[threadIdx.x], smax[threadIdx.x + s]);
        __syncthreads();
    }
    if (threadIdx.x == 0) atomicMax(&g_maxbits, f2o(smax[0]));
}

// ---------------- kernel 4: e_exp = exp(e - max), denom scatter ------------
__global__ void k_expdenom(const int* __restrict__ ei) {
    int e = blockIdx.x * blockDim.x + threadIdx.x;
    if (e >= NE) return;
    float M = o2f(g_maxbits);
    int row = ei[e];
    float4 ev = *(float4*)(g_e + (size_t)e * NH);
    ev.x = __expf(ev.x - M);
    ev.y = __expf(ev.y - M);
    ev.z = __expf(ev.z - M);
    ev.w = __expf(ev.w - M);
    *(float4*)(g_e + (size_t)e * NH) = ev;
    float* d = g_denom + (size_t)row * NH;
    atomicAdd(d + 0, ev.x);
    atomicAdd(d + 1, ev.y);
    atomicAdd(d + 2, ev.z);
    atomicAdd(d + 3, ev.w);
}

// ---------------- kernel 5: att + weighted scatter into h_out --------------
// one warp per edge; lane layout: coalesced 128B gathers/atomics per head chunk
__global__ void k_scatter(const int* __restrict__ ei,
                          float* __restrict__ out_h, float* __restrict__ out_att) {
    int gw = (blockIdx.x * blockDim.x + threadIdx.x) >> 5;
    int lane = threadIdx.x & 31;
    if (gw >= NE) return;
    int e = gw;
    int row = ei[e];
    int col = ei[NE + e];

    float att = 0.0f;
    if (lane < NH) {
        float eexp = g_e[(size_t)e * NH + lane];
        float den = g_denom[(size_t)row * NH + lane];
        att = eexp / (den + 1e-8f);
        out_att[(size_t)e * NH + lane] = att;
    }
    const float* src = g_ht + (size_t)col * HF;
    float* dst = out_h + (size_t)row * HF;
    #pragma unroll
    for (int q = 0; q < NH; q++) {
        float a_h = __shfl_sync(0xffffffffu, att, q);
        float x = src[q * 32 + lane];
        atomicAdd(dst + q * 32 + lane, a_h * x);
    }
}

// ---------------- kernel 6: elu in place -----------------------------------
__global__ void k_elu(float* __restrict__ out_h) {
    int i = blockIdx.x * blockDim.x + threadIdx.x;
    if (i < NN * HF) {
        float x = out_h[i];
        out_h[i] = (x > 0.0f) ? x : expm1f(x);
    }
}

// ---------------- launcher --------------------------------------------------
extern "C" void kernel_launch(void* const* d_in, const int* in_sizes, int n_in,
                              void* d_out, int out_size) {
    (void)in_sizes; (void)n_in; (void)out_size;
    const float* h  = (const float*)d_in[0];
    const int*   ei = (const int*)d_in[1];
    const float* ea = (const float*)d_in[2];
    const float* W  = (const float*)d_in[3];
    const float* a  = (const float*)d_in[4];
    const float* eW = (const float*)d_in[5];
    const float* eb = (const float*)d_in[6];

    float* out_h   = (float*)d_out;                       // [NN, 128]
    float* out_att = (float*)d_out + (size_t)NN * HF;     // [NE, 4]

    cudaMemsetAsync(out_h, 0, (size_t)NN * HF * sizeof(float), 0);

    k_init<<<200, 256>>>(eW, a, eb);
    k_gemm<<<(NN + 127) / 128, 256>>>(h, W);
    k_alpha<<<(NN + 1) / 2, 256>>>(a);
    k_edge<<<(NE + 255) / 256, 256>>>(ei, ea);
    k_expdenom<<<(NE + 255) / 256, 256>>>(ei);
    k_scatter<<<(NE * 32 + 255) / 256, 256>>>(ei, out_h, out_att);
    k_elu<<<(NN * HF + 255) / 256, 256>>>(out_h);
}